// round 9
// baseline (speedup 1.0000x reference)
#include <cuda_runtime.h>
#include <cuda_fp16.h>
#include <cstdint>
#include <math.h>

// ---------------------------------------------------------------------------
// EnhancedXLSTM — round 9: fp16 mma.sync, CTA tile 128x256, warp tile 64x64,
// 3-stage cp.async pipeline.
//   B=16384, D=512, S=3, H=8, HD=64
// ---------------------------------------------------------------------------

namespace cfg {
constexpr int B  = 16384;
constexpr int D  = 512;
constexpr int S  = 3;
constexpr int H  = 8;
constexpr int HD = 64;

constexpr long long N_BD  = (long long)B * D;
constexpr long long N_SBD = (long long)S * B * D;

// fp32 scratch (float units)
constexpr long long XS_OFF     = 0;
constexpr long long GATES_OFF  = XS_OFF    + N_SBD;
constexpr long long QF_OFF     = GATES_OFF + 4 * N_SBD;
constexpr long long KVF_OFF    = QF_OFF    + N_BD;          // combined k|v, S*B x 1024
// fp16 activation scratch (float units)
constexpr long long XH_OFF     = KVF_OFF   + 2 * N_SBD;
constexpr long long HPREVH_OFF = XH_OFF    + N_BD / 2;
constexpr long long XSH_OFF    = HPREVH_OFF + N_SBD / 2;
constexpr long long HNEWH_OFF  = XSH_OFF   + N_SBD / 2;
constexpr long long SSMH_OFF   = HNEWH_OFF + N_SBD / 2;
constexpr long long FBH_OFF    = SSMH_OFF  + N_BD / 2;
// fp16 weight scratch (float units)
constexpr long long WTH_OFF     = FBH_OFF   + N_BD / 2;
constexpr long long WIHH_OFF    = WTH_OFF   + (long long)S * D * D / 2;
constexpr long long WHHH_OFF    = WIHH_OFF  + (long long)S * 4 * D * D / 2;
constexpr long long INPROJH_OFF = WHHH_OFF  + (long long)S * 4 * D * D / 2;
constexpr long long OUTPROJH_OFF= INPROJH_OFF + (long long)3 * D * D / 2;
constexpr long long MIXH_OFF    = OUTPROJH_OFF + (long long)D * D / 2;
constexpr long long SCRATCH_TOTAL = MIXH_OFF + (long long)D * 3 * D / 2;
}

__device__ float g_scratch[cfg::SCRATCH_TOTAL];

// ---------------------------------------------------------------------------
// Conversion helpers
// ---------------------------------------------------------------------------
__device__ __forceinline__ uint2 pack_half4(float4 v) {
    __half2 p0 = __floats2half2_rn(v.x, v.y);
    __half2 p1 = __floats2half2_rn(v.z, v.w);
    uint2 o;
    o.x = *reinterpret_cast<uint32_t*>(&p0);
    o.y = *reinterpret_cast<uint32_t*>(&p1);
    return o;
}

struct CvtJob { const float4* src; void* dst; long long n4; };
template <int NJ> struct CvtJobs { CvtJob j[NJ]; };

template <int NJ>
__global__ __launch_bounds__(256)
void cvt_half_kernel(CvtJobs<NJ> jobs)
{
    long long i = (long long)blockIdx.x * blockDim.x + threadIdx.x;
#pragma unroll
    for (int jj = 0; jj < NJ; ++jj) {
        const CvtJob J = jobs.j[jj];
        if (i < J.n4) {
            ((uint2*)J.dst)[i] = pack_half4(J.src[i]);
            return;
        }
        i -= J.n4;
    }
}

// ---------------------------------------------------------------------------
// MMA / async-copy helpers
// ---------------------------------------------------------------------------
__device__ __forceinline__ uint32_t smem_u32(const void* p) {
    uint32_t a;
    asm("{ .reg .u64 t; cvta.to.shared.u64 t, %1; cvt.u32.u64 %0, t; }" : "=r"(a) : "l"(p));
    return a;
}

#define LDSM_X4(r, addr) \
    asm volatile("ldmatrix.sync.aligned.m8n8.x4.shared.b16 {%0,%1,%2,%3}, [%4];" \
                 : "=r"((r)[0]), "=r"((r)[1]), "=r"((r)[2]), "=r"((r)[3]) : "r"(addr))

__device__ __forceinline__ void mma_f16(float* c, const uint32_t* a, uint32_t b0, uint32_t b1) {
    asm volatile(
        "mma.sync.aligned.m16n8k16.row.col.f32.f16.f16.f32 "
        "{%0,%1,%2,%3}, {%4,%5,%6,%7}, {%8,%9}, {%0,%1,%2,%3};"
        : "+f"(c[0]), "+f"(c[1]), "+f"(c[2]), "+f"(c[3])
        : "r"(a[0]), "r"(a[1]), "r"(a[2]), "r"(a[3]), "r"(b0), "r"(b1));
}

#define CP_ASYNC_16(dst, src) \
    asm volatile("cp.async.cg.shared.global [%0], [%1], 16;" :: "r"(dst), "l"(src) : "memory")
#define CP_COMMIT() asm volatile("cp.async.commit_group;" ::: "memory")
#define CP_WAIT_1() asm volatile("cp.async.wait_group 1;" ::: "memory")

// ---------------------------------------------------------------------------
// GEMM:  C[z][M,N] = sum_seg A_seg[z][M,512] @ W_seg[z][N,512]^T + sum bias
//   A, W: fp16.  CTA tile 128x256, 256 thr, warp tile 64x64, K-chunk 32,
//   3-stage cp.async pipeline. N must be a multiple of 256.
// ---------------------------------------------------------------------------
struct SegH {
    const __half* A; const __half* W; const float* bias;
    long long sA, sW, sB;
    int ldA, ldW;
};
template <int NSEG> struct SegsH { SegH s[NSEG]; };

constexpr int ROW_STRIDE = 80;               // bytes per row (32 halfs + pad)
constexpr int PIECE_A = 128 * ROW_STRIDE;    // 10240
constexpr int PIECE_B = 256 * ROW_STRIDE;    // 20480
constexpr int STAGE = PIECE_A + PIECE_B;     // 30720
constexpr int NSTAGE = 3;
constexpr int OFF_BIAS = NSTAGE * STAGE;     // 92160
constexpr int SMEM_BYTES = OFF_BIAS + 1024;  // 93184

template <int NSEG>
__global__ __launch_bounds__(256, 1)
void mma_gemm_kernel(SegsH<NSEG> segs, float* __restrict__ C,
                     long long strideC, int ldC)
{
    extern __shared__ __align__(16) uint8_t buf[];
    const uint32_t sb = smem_u32(buf);

    const int tid  = threadIdx.x;
    const int wid  = tid >> 5;
    const int lane = tid & 31;
    const int z = blockIdx.z;
    const int rowBlock = blockIdx.y * 128;
    const int colBlock = blockIdx.x * 256;

    // Bias sum for this column block (256 cols; covered by first loop sync)
    {
        float acc = 0.0f;
#pragma unroll
        for (int sgi = 0; sgi < NSEG; ++sgi) {
            const SegH& sg = segs.s[sgi];
            if (sg.bias) acc += sg.bias[z * sg.sB + colBlock + tid];
        }
        reinterpret_cast<float*>(buf + OFF_BIAS)[tid] = acc;
    }

    // cp.async loader mapping. A: 512 16B-slots (2/thread), B: 1024 (4/thread).
    const int rA0 = (tid + 0)   >> 2, qA0 = (tid + 0)   & 3;
    const int rA1 = (tid + 256) >> 2, qA1 = (tid + 256) & 3;

    // ldmatrix mapping: warp grid 2 (M) x 4 (N), warp tile 64x64
    const int warp_m = wid >> 2;      // 0..1
    const int warp_n = wid & 3;       // 0..3
    const int xrow    = (lane & 7) | (((lane >> 3) & 1) << 3);
    const int kb_lane = ((lane >> 4) & 1) * 16;
    uint32_t aOff[4], bOff[4];
#pragma unroll
    for (int mf = 0; mf < 4; ++mf)
        aOff[mf] = (uint32_t)((warp_m * 64 + mf * 16 + xrow) * ROW_STRIDE + kb_lane);
#pragma unroll
    for (int p = 0; p < 4; ++p)
        bOff[p] = (uint32_t)((warp_n * 64 + p * 16 + xrow) * ROW_STRIDE + kb_lane);

    float acc[4][8][4];
#pragma unroll
    for (int mf = 0; mf < 4; ++mf)
#pragma unroll
        for (int nf = 0; nf < 8; ++nf)
#pragma unroll
            for (int e = 0; e < 4; ++e) acc[mf][nf][e] = 0.0f;

    auto cp_stage = [&](int stage, int t) {
        const int sgi = t >> 4;
        const int kc  = t & 15;
        const SegH& sg = segs.s[sgi];
        const __half* Ab = sg.A + (long long)z * sg.sA + (size_t)rowBlock * sg.ldA + kc * 32;
        const __half* Wb = sg.W + (long long)z * sg.sW + (size_t)colBlock * sg.ldW + kc * 32;
        const uint32_t stA = sb + stage * STAGE;
        const uint32_t stB = stA + PIECE_A;
        CP_ASYNC_16(stA + rA0 * ROW_STRIDE + qA0 * 16, Ab + (size_t)rA0 * sg.ldA + qA0 * 8);
        CP_ASYNC_16(stA + rA1 * ROW_STRIDE + qA1 * 16, Ab + (size_t)rA1 * sg.ldA + qA1 * 8);
#pragma unroll
        for (int i = 0; i < 4; ++i) {
            const int slot = tid + i * 256;
            const int rB = slot >> 2, qB = slot & 3;
            CP_ASYNC_16(stB + rB * ROW_STRIDE + qB * 16, Wb + (size_t)rB * sg.ldW + qB * 8);
        }
        CP_COMMIT();
    };

    auto compute = [&](int stage) {
        const uint32_t stA = sb + stage * STAGE;
        const uint32_t stB = stA + PIECE_A;
#pragma unroll
        for (int h = 0; h < 2; ++h) {
            const uint32_t hb = h * 32;
            uint32_t Aa[4][4], Bb[4][4];
#pragma unroll
            for (int mf = 0; mf < 4; ++mf)
                LDSM_X4(Aa[mf], stA + aOff[mf] + hb);
#pragma unroll
            for (int p = 0; p < 4; ++p)
                LDSM_X4(Bb[p], stB + bOff[p] + hb);
#pragma unroll
            for (int mf = 0; mf < 4; ++mf)
#pragma unroll
                for (int nf = 0; nf < 8; ++nf) {
                    const int p = nf >> 1, s = nf & 1;
                    mma_f16(acc[mf][nf], Aa[mf], Bb[p][s], Bb[p][s + 2]);
                }
        }
    };

    const int T = NSEG * 16;           // >= 16
    cp_stage(0, 0);
    cp_stage(1, 1);

#pragma unroll 1
    for (int t = 0; t < T; ++t) {
        CP_WAIT_1();                   // stage t landed (<=1 group pending)
        __syncthreads();
        if (t + 2 < T) cp_stage((t + 2) % NSTAGE, t + 2);
        compute(t % NSTAGE);
    }

    // Epilogue
    const float* biasS = reinterpret_cast<const float*>(buf + OFF_BIAS);
    float* Cb = C + (long long)z * strideC;
#pragma unroll
    for (int mf = 0; mf < 4; ++mf) {
#pragma unroll
        for (int nf = 0; nf < 8; ++nf) {
            const int lcol = warp_n * 64 + nf * 8 + (lane & 3) * 2;
            const int r0   = rowBlock + warp_m * 64 + mf * 16 + (lane >> 2);
            const float b0 = biasS[lcol], b1 = biasS[lcol + 1];
            float2 v0 = {acc[mf][nf][0] + b0, acc[mf][nf][1] + b1};
            float2 v1 = {acc[mf][nf][2] + b0, acc[mf][nf][3] + b1};
            *reinterpret_cast<float2*>(Cb + (size_t)r0 * ldC + colBlock + lcol) = v0;
            *reinterpret_cast<float2*>(Cb + (size_t)(r0 + 8) * ldC + colBlock + lcol) = v1;
        }
    }
}

// ---------------------------------------------------------------------------
// LayerNorm + exact GELU: reads fp32 xs, writes fp16 xs_h
// ---------------------------------------------------------------------------
__global__ __launch_bounds__(128)
void ln_gelu_kernel(const float* __restrict__ xs,
                    __half* __restrict__ xs_h,
                    const float* __restrict__ ln_g,
                    const float* __restrict__ ln_b)
{
    using namespace cfg;
    __shared__ float shm[4];
    const long long row = blockIdx.x;
    const int s = (int)(row / B);
    const float* p = xs + row * D;
    const int t = threadIdx.x;

    float4 v = reinterpret_cast<const float4*>(p)[t];

    float sum = v.x + v.y + v.z + v.w;
#pragma unroll
    for (int o = 16; o; o >>= 1) sum += __shfl_xor_sync(0xffffffffu, sum, o);
    if ((t & 31) == 0) shm[t >> 5] = sum;
    __syncthreads();
    const float mean = (shm[0] + shm[1] + shm[2] + shm[3]) * (1.0f / D);
    __syncthreads();

    const float dx = v.x - mean, dy = v.y - mean, dz = v.z - mean, dw = v.w - mean;
    float ss = dx * dx + dy * dy + dz * dz + dw * dw;
#pragma unroll
    for (int o = 16; o; o >>= 1) ss += __shfl_xor_sync(0xffffffffu, ss, o);
    if ((t & 31) == 0) shm[t >> 5] = ss;
    __syncthreads();
    const float var = (shm[0] + shm[1] + shm[2] + shm[3]) * (1.0f / D);
    const float inv = rsqrtf(var + 1e-5f);

    const float4 g4 = reinterpret_cast<const float4*>(ln_g + (long long)s * D)[t];
    const float4 b4 = reinterpret_cast<const float4*>(ln_b + (long long)s * D)[t];

    const float kInvSqrt2 = 0.70710678118654752f;
    float y;
    float4 o4;
    y = dx * inv * g4.x + b4.x; o4.x = 0.5f * y * (1.0f + erff(y * kInvSqrt2));
    y = dy * inv * g4.y + b4.y; o4.y = 0.5f * y * (1.0f + erff(y * kInvSqrt2));
    y = dz * inv * g4.z + b4.z; o4.z = 0.5f * y * (1.0f + erff(y * kInvSqrt2));
    y = dw * inv * g4.w + b4.w; o4.w = 0.5f * y * (1.0f + erff(y * kInvSqrt2));
    reinterpret_cast<uint2*>(xs_h + row * D)[t] = pack_half4(o4);
}

// ---------------------------------------------------------------------------
// LSTM pointwise: gates -> h_new (fp32 + fp16), c_new
// ---------------------------------------------------------------------------
__device__ __forceinline__ float sigmoidf_(float x) { return 1.0f / (1.0f + expf(-x)); }

__global__ __launch_bounds__(256)
void lstm_kernel(const float* __restrict__ gates,
                 const float* __restrict__ c_prev,
                 const float* __restrict__ decays,
                 float* __restrict__ h_new,
                 __half* __restrict__ hnew_h,
                 float* __restrict__ c_new)
{
    using namespace cfg;
    const long long idx = (long long)blockIdx.x * blockDim.x + threadIdx.x;
    const long long total = (long long)S * B * D;
    if (idx >= total) return;

    const int d = (int)(idx % D);
    const long long bs = idx / D;
    const int b = (int)(bs % B);
    const int s = (int)(bs / B);

    const float* g = gates + ((long long)s * B + b) * (4 * D) + d;
    const float ig = g[0];
    const float fg = g[D];
    const float gg = g[2 * D];
    const float og = g[3 * D];

    const float cp  = c_prev[idx];
    const float c_l = sigmoidf_(fg) * cp + sigmoidf_(ig) * tanhf(gg);
    const float h   = sigmoidf_(og) * tanhf(c_l);
    const float dd  = decays[s];

    h_new[idx]  = h;
    hnew_h[idx] = __float2half_rn(h);
    c_new[idx]  = dd * cp + (1.0f - dd) * c_l;
}

// ---------------------------------------------------------------------------
// Attention over S=3: one warp per (b, h). kv combined: row ld=1024,
// cols [0,512)=k, [512,1024)=v.
// ---------------------------------------------------------------------------
__global__ __launch_bounds__(256)
void attn_kernel(const float* __restrict__ q,
                 const float* __restrict__ kv,
                 __half* __restrict__ fused_h)
{
    using namespace cfg;
    const int gwarp = (int)((blockIdx.x * (long long)blockDim.x + threadIdx.x) >> 5);
    const int lane  = threadIdx.x & 31;
    if (gwarp >= B * H) return;
    const int h = gwarp % H;
    const int b = gwarp / H;

    const float* qp = q + (long long)b * D + h * HD;
    const float q0 = qp[lane];
    const float q1 = qp[lane + 32];

    float logits[S];
#pragma unroll
    for (int s = 0; s < S; s++) {
        const float* kp = kv + ((long long)s * B + b) * (2 * D) + h * HD;
        float dot = q0 * kp[lane] + q1 * kp[lane + 32];
#pragma unroll
        for (int o = 16; o; o >>= 1) dot += __shfl_xor_sync(0xffffffffu, dot, o);
        logits[s] = dot * 0.125f;
    }
    float mx = fmaxf(logits[0], fmaxf(logits[1], logits[2]));
    float e0 = expf(logits[0] - mx);
    float e1 = expf(logits[1] - mx);
    float e2 = expf(logits[2] - mx);
    const float rs = 1.0f / (e0 + e1 + e2);
    e0 *= rs; e1 *= rs; e2 *= rs;

    float o0 = 0.0f, o1 = 0.0f;
    const float w[S] = {e0, e1, e2};
#pragma unroll
    for (int s = 0; s < S; s++) {
        const float* vp = kv + ((long long)s * B + b) * (2 * D) + D + h * HD;
        o0 = fmaf(w[s], vp[lane],      o0);
        o1 = fmaf(w[s], vp[lane + 32], o1);
    }
    __half* fp = fused_h + (long long)b * D + h * HD;
    fp[lane]      = __float2half_rn(o0);
    fp[lane + 32] = __float2half_rn(o1);
}

// ---------------------------------------------------------------------------
// Launcher
// ---------------------------------------------------------------------------
extern "C" void kernel_launch(void* const* d_in, const int* in_sizes, int n_in,
                              void* d_out, int out_size)
{
    using namespace cfg;
    const float* x          = (const float*)d_in[0];
    const float* h_prev     = (const float*)d_in[1];
    const float* c_prev     = (const float*)d_in[2];
    const float* ssm_state  = (const float*)d_in[3];
    const float* Wt         = (const float*)d_in[4];
    const float* bt         = (const float*)d_in[5];
    const float* ln_g       = (const float*)d_in[6];
    const float* ln_b       = (const float*)d_in[7];
    const float* W_ih       = (const float*)d_in[8];
    const float* W_hh       = (const float*)d_in[9];
    const float* b_ih       = (const float*)d_in[10];
    const float* b_hh       = (const float*)d_in[11];
    const float* decays     = (const float*)d_in[12];
    const float* in_proj_w  = (const float*)d_in[13];
    const float* in_proj_b  = (const float*)d_in[14];
    const float* out_proj_w = (const float*)d_in[15];
    const float* out_proj_b = (const float*)d_in[16];
    const float* mix_w      = (const float*)d_in[17];
    const float* mix_b      = (const float*)d_in[18];

    float* out   = (float*)d_out;
    float* h_new = out + N_BD;
    float* c_new = h_new + N_SBD;

    float* scratch = nullptr;
    cudaGetSymbolAddress((void**)&scratch, g_scratch);
    float* xs    = scratch + XS_OFF;
    float* gates = scratch + GATES_OFF;
    float* qf    = scratch + QF_OFF;
    float* kvf   = scratch + KVF_OFF;
    __half* x_h     = (__half*)(scratch + XH_OFF);
    __half* hprev_h = (__half*)(scratch + HPREVH_OFF);
    __half* xs_h    = (__half*)(scratch + XSH_OFF);
    __half* hnew_h  = (__half*)(scratch + HNEWH_OFF);
    __half* ssm_h   = (__half*)(scratch + SSMH_OFF);
    __half* fb_h    = (__half*)(scratch + FBH_OFF);
    __half* Wt_h      = (__half*)(scratch + WTH_OFF);
    __half* Wih_h     = (__half*)(scratch + WIHH_OFF);
    __half* Whh_h     = (__half*)(scratch + WHHH_OFF);
    __half* inproj_h  = (__half*)(scratch + INPROJH_OFF);
    __half* outproj_h = (__half*)(scratch + OUTPROJH_OFF);
    __half* mix_h     = (__half*)(scratch + MIXH_OFF);

    cudaFuncSetAttribute(mma_gemm_kernel<1>, cudaFuncAttributeMaxDynamicSharedMemorySize, SMEM_BYTES);
    cudaFuncSetAttribute(mma_gemm_kernel<2>, cudaFuncAttributeMaxDynamicSharedMemorySize, SMEM_BYTES);
    cudaFuncSetAttribute(mma_gemm_kernel<4>, cudaFuncAttributeMaxDynamicSharedMemorySize, SMEM_BYTES);

    const dim3 blk(256);

    // --- launch 0: convert weights + x + h_prev + ssm to fp16 ---
    {
        CvtJobs<9> jobs;
        jobs.j[0] = {(const float4*)Wt,         Wt_h,      (long long)S * D * D / 4};
        jobs.j[1] = {(const float4*)W_ih,       Wih_h,     (long long)S * 4 * D * D / 4};
        jobs.j[2] = {(const float4*)W_hh,       Whh_h,     (long long)S * 4 * D * D / 4};
        jobs.j[3] = {(const float4*)in_proj_w,  inproj_h,  (long long)3 * D * D / 4};
        jobs.j[4] = {(const float4*)out_proj_w, outproj_h, (long long)D * D / 4};
        jobs.j[5] = {(const float4*)mix_w,      mix_h,     (long long)D * 3 * D / 4};
        jobs.j[6] = {(const float4*)x,          x_h,       N_BD / 4};
        jobs.j[7] = {(const float4*)h_prev,     hprev_h,   N_SBD / 4};
        jobs.j[8] = {(const float4*)ssm_state,  ssm_h,     N_BD / 4};
        long long tot = 0;
        for (int i = 0; i < 9; ++i) tot += jobs.j[i].n4;
        cvt_half_kernel<9><<<(int)((tot + 255) / 256), 256>>>(jobs);
    }

    // --- launch 1: xs[s] = x @ Wt[s]^T + bt[s] ---
    {
        SegsH<1> sg;
        sg.s[0] = {x_h, Wt_h, bt, 0, (long long)D * D, D, D, D};
        mma_gemm_kernel<1><<<dim3(D / 256, B / 128, S), blk, SMEM_BYTES>>>(sg, xs, N_BD, D);
    }

    // --- launch 2: LN + GELU -> xs_h ---
    ln_gelu_kernel<<<S * B, 128>>>(xs, xs_h, ln_g, ln_b);

    // --- launch 3: gates = xs@W_ih^T + b_ih + h_prev@W_hh^T + b_hh ---
    {
        SegsH<2> sg;
        sg.s[0] = {xs_h,    Wih_h, b_ih, N_BD, (long long)4 * D * D, 4 * D, D, D};
        sg.s[1] = {hprev_h, Whh_h, b_hh, N_BD, (long long)4 * D * D, 4 * D, D, D};
        mma_gemm_kernel<2><<<dim3(4 * D / 256, B / 128, S), blk, SMEM_BYTES>>>(
            sg, gates, (long long)B * 4 * D, 4 * D);
    }

    // --- launch 4: LSTM pointwise ---
    lstm_kernel<<<(int)((N_SBD + 255) / 256), 256>>>(
        gates, c_prev, decays, h_new, hnew_h, c_new);

    // --- launch 5 (profiled): fused k|v = h_new @ [Wk;Wv]^T + [bk;bv], N=1024 ---
    {
        SegsH<1> sg;
        sg.s[0] = {hnew_h, inproj_h + (long long)D * D, in_proj_b + D, N_BD, 0, 0, D, D};
        mma_gemm_kernel<1><<<dim3(2 * D / 256, B / 128, S), blk, SMEM_BYTES>>>(
            sg, kvf, 2 * N_BD, 2 * D);
    }

    // --- launch 6: q ---
    {
        SegsH<1> sg;
        sg.s[0] = {ssm_h, inproj_h, in_proj_b, 0, 0, 0, D, D};
        mma_gemm_kernel<1><<<dim3(D / 256, B / 128, 1), blk, SMEM_BYTES>>>(sg, qf, 0, D);
    }

    // --- launch 7: attention -> fb_h ---
    attn_kernel<<<(B * H) / 8, 256>>>(qf, kvf, fb_h);

    // --- launch 8: out = fused@out_proj^T + sum_s h_new[s]@mix_w[:,sD:]^T + biases ---
    {
        SegsH<4> sg;
        sg.s[0] = {fb_h,               outproj_h,     out_proj_b, 0, 0, 0, D, D};
        sg.s[1] = {hnew_h,             mix_h,         mix_b,      0, 0, 0, D, S * D};
        sg.s[2] = {hnew_h + N_BD,      mix_h + D,     nullptr,    0, 0, 0, D, S * D};
        sg.s[3] = {hnew_h + 2 * N_BD,  mix_h + 2 * D, nullptr,    0, 0, 0, D, S * D};
        mma_gemm_kernel<4><<<dim3(D / 256, B / 128, 1), blk, SMEM_BYTES>>>(sg, out, 0, D);
    }
}

// round 10
// speedup vs baseline: 1.0944x; 1.0944x over previous
#include <cuda_runtime.h>
#include <cuda_fp16.h>
#include <cstdint>
#include <math.h>

// ---------------------------------------------------------------------------
// EnhancedXLSTM — round 10: round-8 config (128x128 CTA tile, 64x32 warp tile,
// 2 CTAs/SM) + K=64 per smem stage (half the barriers), 2-stage cp.async.
//   B=16384, D=512, S=3, H=8, HD=64
// ---------------------------------------------------------------------------

namespace cfg {
constexpr int B  = 16384;
constexpr int D  = 512;
constexpr int S  = 3;
constexpr int H  = 8;
constexpr int HD = 64;

constexpr long long N_BD  = (long long)B * D;
constexpr long long N_SBD = (long long)S * B * D;

// fp32 scratch (float units)
constexpr long long XS_OFF     = 0;
constexpr long long GATES_OFF  = XS_OFF    + N_SBD;
constexpr long long QF_OFF     = GATES_OFF + 4 * N_SBD;
constexpr long long KVF_OFF    = QF_OFF    + N_BD;          // combined k|v, S*B x 1024
// fp16 activation scratch (float units)
constexpr long long XH_OFF     = KVF_OFF   + 2 * N_SBD;
constexpr long long HPREVH_OFF = XH_OFF    + N_BD / 2;
constexpr long long XSH_OFF    = HPREVH_OFF + N_SBD / 2;
constexpr long long HNEWH_OFF  = XSH_OFF   + N_SBD / 2;
constexpr long long SSMH_OFF   = HNEWH_OFF + N_SBD / 2;
constexpr long long FBH_OFF    = SSMH_OFF  + N_BD / 2;
// fp16 weight scratch (float units)
constexpr long long WTH_OFF     = FBH_OFF   + N_BD / 2;
constexpr long long WIHH_OFF    = WTH_OFF   + (long long)S * D * D / 2;
constexpr long long WHHH_OFF    = WIHH_OFF  + (long long)S * 4 * D * D / 2;
constexpr long long INPROJH_OFF = WHHH_OFF  + (long long)S * 4 * D * D / 2;
constexpr long long OUTPROJH_OFF= INPROJH_OFF + (long long)3 * D * D / 2;
constexpr long long MIXH_OFF    = OUTPROJH_OFF + (long long)D * D / 2;
constexpr long long SCRATCH_TOTAL = MIXH_OFF + (long long)D * 3 * D / 2;
}

__device__ float g_scratch[cfg::SCRATCH_TOTAL];

// ---------------------------------------------------------------------------
// Conversion helpers
// ---------------------------------------------------------------------------
__device__ __forceinline__ uint2 pack_half4(float4 v) {
    __half2 p0 = __floats2half2_rn(v.x, v.y);
    __half2 p1 = __floats2half2_rn(v.z, v.w);
    uint2 o;
    o.x = *reinterpret_cast<uint32_t*>(&p0);
    o.y = *reinterpret_cast<uint32_t*>(&p1);
    return o;
}

struct CvtJob { const float4* src; void* dst; long long n4; };
template <int NJ> struct CvtJobs { CvtJob j[NJ]; };

template <int NJ>
__global__ __launch_bounds__(256)
void cvt_half_kernel(CvtJobs<NJ> jobs)
{
    long long i = (long long)blockIdx.x * blockDim.x + threadIdx.x;
#pragma unroll
    for (int jj = 0; jj < NJ; ++jj) {
        const CvtJob J = jobs.j[jj];
        if (i < J.n4) {
            ((uint2*)J.dst)[i] = pack_half4(J.src[i]);
            return;
        }
        i -= J.n4;
    }
}

// ---------------------------------------------------------------------------
// MMA / async-copy helpers
// ---------------------------------------------------------------------------
__device__ __forceinline__ uint32_t smem_u32(const void* p) {
    uint32_t a;
    asm("{ .reg .u64 t; cvta.to.shared.u64 t, %1; cvt.u32.u64 %0, t; }" : "=r"(a) : "l"(p));
    return a;
}

#define LDSM_X4(r, addr) \
    asm volatile("ldmatrix.sync.aligned.m8n8.x4.shared.b16 {%0,%1,%2,%3}, [%4];" \
                 : "=r"((r)[0]), "=r"((r)[1]), "=r"((r)[2]), "=r"((r)[3]) : "r"(addr))

__device__ __forceinline__ void mma_f16(float* c, const uint32_t* a, uint32_t b0, uint32_t b1) {
    asm volatile(
        "mma.sync.aligned.m16n8k16.row.col.f32.f16.f16.f32 "
        "{%0,%1,%2,%3}, {%4,%5,%6,%7}, {%8,%9}, {%0,%1,%2,%3};"
        : "+f"(c[0]), "+f"(c[1]), "+f"(c[2]), "+f"(c[3])
        : "r"(a[0]), "r"(a[1]), "r"(a[2]), "r"(a[3]), "r"(b0), "r"(b1));
}

#define CP_ASYNC_16(dst, src) \
    asm volatile("cp.async.cg.shared.global [%0], [%1], 16;" :: "r"(dst), "l"(src) : "memory")
#define CP_COMMIT()   asm volatile("cp.async.commit_group;" ::: "memory")
#define CP_WAIT_ALL() asm volatile("cp.async.wait_group 0;" ::: "memory")

// ---------------------------------------------------------------------------
// GEMM:  C[z][M,N] = sum_seg A_seg[z][M,512] @ W_seg[z][N,512]^T + sum bias
//   A, W: fp16.  CTA tile 128x128, 256 thr, warp tile 64x32.
//   K per stage = 64 (two 32-wide sub-chunks), 2-stage cp.async.
// ---------------------------------------------------------------------------
struct SegH {
    const __half* A; const __half* W; const float* bias;
    long long sA, sW, sB;
    int ldA, ldW;
};
template <int NSEG> struct SegsH { SegH s[NSEG]; };

constexpr int ROW_STRIDE = 80;               // bytes per 32-half row (+pad)
constexpr int SUB = 128 * ROW_STRIDE;        // one 128x32 sub-chunk = 10240 B
constexpr int PIECE = 2 * SUB;               // K=64 piece per matrix = 20480 B
constexpr int STAGE = 2 * PIECE;             // A + B = 40960 B
constexpr int NSTAGE = 2;
constexpr int OFF_BIAS = NSTAGE * STAGE;     // 81920
constexpr int SMEM_BYTES = OFF_BIAS + 512;   // 82432  (2 CTAs x 82KB fits 228KB)

template <int NSEG>
__global__ __launch_bounds__(256, 2)
void mma_gemm_kernel(SegsH<NSEG> segs, float* __restrict__ C,
                     long long strideC, int ldC)
{
    extern __shared__ __align__(16) uint8_t buf[];
    const uint32_t sb = smem_u32(buf);

    const int tid  = threadIdx.x;
    const int wid  = tid >> 5;
    const int lane = tid & 31;
    const int z = blockIdx.z;
    const int rowBlock = blockIdx.y * 128;
    const int colBlock = blockIdx.x * 128;

    // Bias sum for this column block (covered by first loop __syncthreads)
    if (tid < 128) {
        float acc = 0.0f;
#pragma unroll
        for (int sgi = 0; sgi < NSEG; ++sgi) {
            const SegH& sg = segs.s[sgi];
            if (sg.bias) acc += sg.bias[z * sg.sB + colBlock + tid];
        }
        reinterpret_cast<float*>(buf + OFF_BIAS)[tid] = acc;
    }

    // cp.async loader mapping: per sub-chunk, 512 16B-slots per matrix (2/thread).
    const int r0s = (tid + 0)   >> 2, q0s = (tid + 0)   & 3;
    const int r1s = (tid + 256) >> 2, q1s = (tid + 256) & 3;

    // ldmatrix mapping (64x32 warp tile; warp grid 2 x 4)
    const int warp_m = wid >> 2;
    const int warp_n = wid & 3;
    const int xrow    = (lane & 7) | (((lane >> 3) & 1) << 3);
    const int kb_lane = ((lane >> 4) & 1) * 16;
    uint32_t aOff[4], bOff[2];
#pragma unroll
    for (int mf = 0; mf < 4; ++mf)
        aOff[mf] = (uint32_t)((warp_m * 64 + mf * 16 + xrow) * ROW_STRIDE + kb_lane);
#pragma unroll
    for (int p = 0; p < 2; ++p)
        bOff[p] = (uint32_t)((warp_n * 32 + p * 16 + xrow) * ROW_STRIDE + kb_lane);

    float acc[4][4][4];
#pragma unroll
    for (int mf = 0; mf < 4; ++mf)
#pragma unroll
        for (int nf = 0; nf < 4; ++nf)
#pragma unroll
            for (int e = 0; e < 4; ++e) acc[mf][nf][e] = 0.0f;

    // Load one K=64 stage (two 32-wide sub-chunks for A and B)
    auto cp_stage = [&](int stage, int t) {
        const int sgi = t >> 3;          // 8 stages of K=64 per 512-K segment
        const int kc2 = t & 7;
        const SegH& sg = segs.s[sgi];
        const __half* Ab = sg.A + (long long)z * sg.sA + (size_t)rowBlock * sg.ldA + kc2 * 64;
        const __half* Wb = sg.W + (long long)z * sg.sW + (size_t)colBlock * sg.ldW + kc2 * 64;
        const uint32_t stA = sb + stage * STAGE;
        const uint32_t stB = stA + PIECE;
#pragma unroll
        for (int sub = 0; sub < 2; ++sub) {
            const uint32_t so = sub * SUB;
            const int ko = sub * 32;
            CP_ASYNC_16(stA + so + r0s * ROW_STRIDE + q0s * 16, Ab + (size_t)r0s * sg.ldA + ko + q0s * 8);
            CP_ASYNC_16(stA + so + r1s * ROW_STRIDE + q1s * 16, Ab + (size_t)r1s * sg.ldA + ko + q1s * 8);
            CP_ASYNC_16(stB + so + r0s * ROW_STRIDE + q0s * 16, Wb + (size_t)r0s * sg.ldW + ko + q0s * 8);
            CP_ASYNC_16(stB + so + r1s * ROW_STRIDE + q1s * 16, Wb + (size_t)r1s * sg.ldW + ko + q1s * 8);
        }
        CP_COMMIT();
    };

    // Compute one K=64 stage: 4 half-chunks, straight-line for scheduling.
    auto compute = [&](int stage) {
        const uint32_t stA = sb + stage * STAGE;
        const uint32_t stB = stA + PIECE;
#pragma unroll
        for (int sub = 0; sub < 2; ++sub) {
            const uint32_t so = sub * SUB;
#pragma unroll
            for (int h = 0; h < 2; ++h) {
                const uint32_t hb = h * 32;
                uint32_t Aa[4][4], Bb[2][4];
#pragma unroll
                for (int mf = 0; mf < 4; ++mf)
                    LDSM_X4(Aa[mf], stA + so + aOff[mf] + hb);
#pragma unroll
                for (int p = 0; p < 2; ++p)
                    LDSM_X4(Bb[p], stB + so + bOff[p] + hb);
#pragma unroll
                for (int mf = 0; mf < 4; ++mf)
#pragma unroll
                    for (int nf = 0; nf < 4; ++nf) {
                        const int p = nf >> 1, s = nf & 1;
                        mma_f16(acc[mf][nf], Aa[mf], Bb[p][s], Bb[p][s + 2]);
                    }
            }
        }
    };

    const int T = NSEG * 8;              // K=64 stages total
    cp_stage(0, 0);

#pragma unroll 1
    for (int t = 0; t < T; ++t) {
        CP_WAIT_ALL();                   // stage t data landed
        __syncthreads();                 // all warps past compute(t-1)
        if (t + 1 < T) cp_stage((t + 1) & 1, t + 1);   // overwrites buffer computed at t-1
        compute(t & 1);
    }

    // Epilogue
    const float* biasS = reinterpret_cast<const float*>(buf + OFF_BIAS);
    float* Cb = C + (long long)z * strideC;
#pragma unroll
    for (int mf = 0; mf < 4; ++mf) {
#pragma unroll
        for (int nf = 0; nf < 4; ++nf) {
            const int lcol = warp_n * 32 + nf * 8 + (lane & 3) * 2;
            const int r0   = rowBlock + warp_m * 64 + mf * 16 + (lane >> 2);
            const float b0 = biasS[lcol], b1 = biasS[lcol + 1];
            float2 v0 = {acc[mf][nf][0] + b0, acc[mf][nf][1] + b1};
            float2 v1 = {acc[mf][nf][2] + b0, acc[mf][nf][3] + b1};
            *reinterpret_cast<float2*>(Cb + (size_t)r0 * ldC + colBlock + lcol) = v0;
            *reinterpret_cast<float2*>(Cb + (size_t)(r0 + 8) * ldC + colBlock + lcol) = v1;
        }
    }
}

// ---------------------------------------------------------------------------
// LayerNorm + exact GELU: reads fp32 xs, writes fp16 xs_h
// ---------------------------------------------------------------------------
__global__ __launch_bounds__(128)
void ln_gelu_kernel(const float* __restrict__ xs,
                    __half* __restrict__ xs_h,
                    const float* __restrict__ ln_g,
                    const float* __restrict__ ln_b)
{
    using namespace cfg;
    __shared__ float shm[4];
    const long long row = blockIdx.x;
    const int s = (int)(row / B);
    const float* p = xs + row * D;
    const int t = threadIdx.x;

    float4 v = reinterpret_cast<const float4*>(p)[t];

    float sum = v.x + v.y + v.z + v.w;
#pragma unroll
    for (int o = 16; o; o >>= 1) sum += __shfl_xor_sync(0xffffffffu, sum, o);
    if ((t & 31) == 0) shm[t >> 5] = sum;
    __syncthreads();
    const float mean = (shm[0] + shm[1] + shm[2] + shm[3]) * (1.0f / D);
    __syncthreads();

    const float dx = v.x - mean, dy = v.y - mean, dz = v.z - mean, dw = v.w - mean;
    float ss = dx * dx + dy * dy + dz * dz + dw * dw;
#pragma unroll
    for (int o = 16; o; o >>= 1) ss += __shfl_xor_sync(0xffffffffu, ss, o);
    if ((t & 31) == 0) shm[t >> 5] = ss;
    __syncthreads();
    const float var = (shm[0] + shm[1] + shm[2] + shm[3]) * (1.0f / D);
    const float inv = rsqrtf(var + 1e-5f);

    const float4 g4 = reinterpret_cast<const float4*>(ln_g + (long long)s * D)[t];
    const float4 b4 = reinterpret_cast<const float4*>(ln_b + (long long)s * D)[t];

    const float kInvSqrt2 = 0.70710678118654752f;
    float y;
    float4 o4;
    y = dx * inv * g4.x + b4.x; o4.x = 0.5f * y * (1.0f + erff(y * kInvSqrt2));
    y = dy * inv * g4.y + b4.y; o4.y = 0.5f * y * (1.0f + erff(y * kInvSqrt2));
    y = dz * inv * g4.z + b4.z; o4.z = 0.5f * y * (1.0f + erff(y * kInvSqrt2));
    y = dw * inv * g4.w + b4.w; o4.w = 0.5f * y * (1.0f + erff(y * kInvSqrt2));
    reinterpret_cast<uint2*>(xs_h + row * D)[t] = pack_half4(o4);
}

// ---------------------------------------------------------------------------
// LSTM pointwise: gates -> h_new (fp32 + fp16), c_new
// ---------------------------------------------------------------------------
__device__ __forceinline__ float sigmoidf_(float x) { return 1.0f / (1.0f + expf(-x)); }

__global__ __launch_bounds__(256)
void lstm_kernel(const float* __restrict__ gates,
                 const float* __restrict__ c_prev,
                 const float* __restrict__ decays,
                 float* __restrict__ h_new,
                 __half* __restrict__ hnew_h,
                 float* __restrict__ c_new)
{
    using namespace cfg;
    const long long idx = (long long)blockIdx.x * blockDim.x + threadIdx.x;
    const long long total = (long long)S * B * D;
    if (idx >= total) return;

    const int d = (int)(idx % D);
    const long long bs = idx / D;
    const int b = (int)(bs % B);
    const int s = (int)(bs / B);

    const float* g = gates + ((long long)s * B + b) * (4 * D) + d;
    const float ig = g[0];
    const float fg = g[D];
    const float gg = g[2 * D];
    const float og = g[3 * D];

    const float cp  = c_prev[idx];
    const float c_l = sigmoidf_(fg) * cp + sigmoidf_(ig) * tanhf(gg);
    const float h   = sigmoidf_(og) * tanhf(c_l);
    const float dd  = decays[s];

    h_new[idx]  = h;
    hnew_h[idx] = __float2half_rn(h);
    c_new[idx]  = dd * cp + (1.0f - dd) * c_l;
}

// ---------------------------------------------------------------------------
// Attention over S=3: one warp per (b, h). kv combined: row ld=1024,
// cols [0,512)=k, [512,1024)=v.
// ---------------------------------------------------------------------------
__global__ __launch_bounds__(256)
void attn_kernel(const float* __restrict__ q,
                 const float* __restrict__ kv,
                 __half* __restrict__ fused_h)
{
    using namespace cfg;
    const int gwarp = (int)((blockIdx.x * (long long)blockDim.x + threadIdx.x) >> 5);
    const int lane  = threadIdx.x & 31;
    if (gwarp >= B * H) return;
    const int h = gwarp % H;
    const int b = gwarp / H;

    const float* qp = q + (long long)b * D + h * HD;
    const float q0 = qp[lane];
    const float q1 = qp[lane + 32];

    float logits[S];
#pragma unroll
    for (int s = 0; s < S; s++) {
        const float* kp = kv + ((long long)s * B + b) * (2 * D) + h * HD;
        float dot = q0 * kp[lane] + q1 * kp[lane + 32];
#pragma unroll
        for (int o = 16; o; o >>= 1) dot += __shfl_xor_sync(0xffffffffu, dot, o);
        logits[s] = dot * 0.125f;
    }
    float mx = fmaxf(logits[0], fmaxf(logits[1], logits[2]));
    float e0 = expf(logits[0] - mx);
    float e1 = expf(logits[1] - mx);
    float e2 = expf(logits[2] - mx);
    const float rs = 1.0f / (e0 + e1 + e2);
    e0 *= rs; e1 *= rs; e2 *= rs;

    float o0 = 0.0f, o1 = 0.0f;
    const float w[S] = {e0, e1, e2};
#pragma unroll
    for (int s = 0; s < S; s++) {
        const float* vp = kv + ((long long)s * B + b) * (2 * D) + D + h * HD;
        o0 = fmaf(w[s], vp[lane],      o0);
        o1 = fmaf(w[s], vp[lane + 32], o1);
    }
    __half* fp = fused_h + (long long)b * D + h * HD;
    fp[lane]      = __float2half_rn(o0);
    fp[lane + 32] = __float2half_rn(o1);
}

// ---------------------------------------------------------------------------
// Launcher
// ---------------------------------------------------------------------------
extern "C" void kernel_launch(void* const* d_in, const int* in_sizes, int n_in,
                              void* d_out, int out_size)
{
    using namespace cfg;
    const float* x          = (const float*)d_in[0];
    const float* h_prev     = (const float*)d_in[1];
    const float* c_prev     = (const float*)d_in[2];
    const float* ssm_state  = (const float*)d_in[3];
    const float* Wt         = (const float*)d_in[4];
    const float* bt         = (const float*)d_in[5];
    const float* ln_g       = (const float*)d_in[6];
    const float* ln_b       = (const float*)d_in[7];
    const float* W_ih       = (const float*)d_in[8];
    const float* W_hh       = (const float*)d_in[9];
    const float* b_ih       = (const float*)d_in[10];
    const float* b_hh       = (const float*)d_in[11];
    const float* decays     = (const float*)d_in[12];
    const float* in_proj_w  = (const float*)d_in[13];
    const float* in_proj_b  = (const float*)d_in[14];
    const float* out_proj_w = (const float*)d_in[15];
    const float* out_proj_b = (const float*)d_in[16];
    const float* mix_w      = (const float*)d_in[17];
    const float* mix_b      = (const float*)d_in[18];

    float* out   = (float*)d_out;
    float* h_new = out + N_BD;
    float* c_new = h_new + N_SBD;

    float* scratch = nullptr;
    cudaGetSymbolAddress((void**)&scratch, g_scratch);
    float* xs    = scratch + XS_OFF;
    float* gates = scratch + GATES_OFF;
    float* qf    = scratch + QF_OFF;
    float* kvf   = scratch + KVF_OFF;
    __half* x_h     = (__half*)(scratch + XH_OFF);
    __half* hprev_h = (__half*)(scratch + HPREVH_OFF);
    __half* xs_h    = (__half*)(scratch + XSH_OFF);
    __half* hnew_h  = (__half*)(scratch + HNEWH_OFF);
    __half* ssm_h   = (__half*)(scratch + SSMH_OFF);
    __half* fb_h    = (__half*)(scratch + FBH_OFF);
    __half* Wt_h      = (__half*)(scratch + WTH_OFF);
    __half* Wih_h     = (__half*)(scratch + WIHH_OFF);
    __half* Whh_h     = (__half*)(scratch + WHHH_OFF);
    __half* inproj_h  = (__half*)(scratch + INPROJH_OFF);
    __half* outproj_h = (__half*)(scratch + OUTPROJH_OFF);
    __half* mix_h     = (__half*)(scratch + MIXH_OFF);

    cudaFuncSetAttribute(mma_gemm_kernel<1>, cudaFuncAttributeMaxDynamicSharedMemorySize, SMEM_BYTES);
    cudaFuncSetAttribute(mma_gemm_kernel<2>, cudaFuncAttributeMaxDynamicSharedMemorySize, SMEM_BYTES);
    cudaFuncSetAttribute(mma_gemm_kernel<4>, cudaFuncAttributeMaxDynamicSharedMemorySize, SMEM_BYTES);

    const dim3 blk(256);

    // --- launch 0: convert weights + x + h_prev + ssm to fp16 ---
    {
        CvtJobs<9> jobs;
        jobs.j[0] = {(const float4*)Wt,         Wt_h,      (long long)S * D * D / 4};
        jobs.j[1] = {(const float4*)W_ih,       Wih_h,     (long long)S * 4 * D * D / 4};
        jobs.j[2] = {(const float4*)W_hh,       Whh_h,     (long long)S * 4 * D * D / 4};
        jobs.j[3] = {(const float4*)in_proj_w,  inproj_h,  (long long)3 * D * D / 4};
        jobs.j[4] = {(const float4*)out_proj_w, outproj_h, (long long)D * D / 4};
        jobs.j[5] = {(const float4*)mix_w,      mix_h,     (long long)D * 3 * D / 4};
        jobs.j[6] = {(const float4*)x,          x_h,       N_BD / 4};
        jobs.j[7] = {(const float4*)h_prev,     hprev_h,   N_SBD / 4};
        jobs.j[8] = {(const float4*)ssm_state,  ssm_h,     N_BD / 4};
        long long tot = 0;
        for (int i = 0; i < 9; ++i) tot += jobs.j[i].n4;
        cvt_half_kernel<9><<<(int)((tot + 255) / 256), 256>>>(jobs);
    }

    // --- launch 1: xs[s] = x @ Wt[s]^T + bt[s] ---
    {
        SegsH<1> sg;
        sg.s[0] = {x_h, Wt_h, bt, 0, (long long)D * D, D, D, D};
        mma_gemm_kernel<1><<<dim3(D / 128, B / 128, S), blk, SMEM_BYTES>>>(sg, xs, N_BD, D);
    }

    // --- launch 2: LN + GELU -> xs_h ---
    ln_gelu_kernel<<<S * B, 128>>>(xs, xs_h, ln_g, ln_b);

    // --- launch 3: gates = xs@W_ih^T + b_ih + h_prev@W_hh^T + b_hh ---
    {
        SegsH<2> sg;
        sg.s[0] = {xs_h,    Wih_h, b_ih, N_BD, (long long)4 * D * D, 4 * D, D, D};
        sg.s[1] = {hprev_h, Whh_h, b_hh, N_BD, (long long)4 * D * D, 4 * D, D, D};
        mma_gemm_kernel<2><<<dim3(4 * D / 128, B / 128, S), blk, SMEM_BYTES>>>(
            sg, gates, (long long)B * 4 * D, 4 * D);
    }

    // --- launch 4: LSTM pointwise ---
    lstm_kernel<<<(int)((N_SBD + 255) / 256), 256>>>(
        gates, c_prev, decays, h_new, hnew_h, c_new);

    // --- launch 5 (profiled): fused k|v = h_new @ [Wk;Wv]^T + [bk;bv], N=1024 ---
    {
        SegsH<1> sg;
        sg.s[0] = {hnew_h, inproj_h + (long long)D * D, in_proj_b + D, N_BD, 0, 0, D, D};
        mma_gemm_kernel<1><<<dim3(2 * D / 128, B / 128, S), blk, SMEM_BYTES>>>(
            sg, kvf, 2 * N_BD, 2 * D);
    }

    // --- launch 6: q ---
    {
        SegsH<1> sg;
        sg.s[0] = {ssm_h, inproj_h, in_proj_b, 0, 0, 0, D, D};
        mma_gemm_kernel<1><<<dim3(D / 128, B / 128, 1), blk, SMEM_BYTES>>>(sg, qf, 0, D);
    }

    // --- launch 7: attention -> fb_h ---
    attn_kernel<<<(B * H) / 8, 256>>>(qf, kvf, fb_h);

    // --- launch 8: out = fused@out_proj^T + sum_s h_new[s]@mix_w[:,sD:]^T + biases ---
    {
        SegsH<4> sg;
        sg.s[0] = {fb_h,               outproj_h,     out_proj_b, 0, 0, 0, D, D};
        sg.s[1] = {hnew_h,             mix_h,         mix_b,      0, 0, 0, D, S * D};
        sg.s[2] = {hnew_h + N_BD,      mix_h + D,     nullptr,    0, 0, 0, D, S * D};
        sg.s[3] = {hnew_h + 2 * N_BD,  mix_h + 2 * D, nullptr,    0, 0, 0, D, S * D};
        mma_gemm_kernel<4><<<dim3(D / 128, B / 128, 1), blk, SMEM_BYTES>>>(sg, out, 0, D);
    }
}